// round 15
// baseline (speedup 1.0000x reference)
#include <cuda_runtime.h>
#include <cuda_bf16.h>
#include <math.h>
#include <stdint.h>

#define FULL 0xffffffffu

__device__ float g_y[32 * 128];   // gelu(LN1(token) @ w_tok + b_tok), unnormalized

__device__ __forceinline__ float gelu_exact(float z) {
    return 0.5f * z * (1.0f + erff(z * 0.70710678118654752f));
}

// Branch-free gelu via Abramowitz-Stegun 7.1.26 erf (|eps| < 1.5e-7 abs).
__device__ __forceinline__ float gelu_fast(float z) {
    const float xs = fabsf(z) * 0.70710678118654752f;
    const float t = __fdividef(1.0f, fmaf(0.3275911f, xs, 1.0f));
    float poly = fmaf(1.061405429f, t, -1.453152027f);
    poly = fmaf(poly, t, 1.421413741f);
    poly = fmaf(poly, t, -0.284496736f);
    poly = fmaf(poly, t, 0.254829592f);
    poly *= t;
    const float erfc_v = poly * __expf(-xs * xs);   // 1 - erf(xs), xs >= 0
    const float hz = 0.5f * z;
    return (z >= 0.f) ? hz * (2.0f - erfc_v) : hz * erfc_v;
}

__device__ __forceinline__ uint32_t smem_u32(const void* p) {
    uint32_t a;
    asm("{ .reg .u64 t; cvta.to.shared.u64 t, %1; cvt.u32.u64 %0, t; }"
        : "=r"(a) : "l"(p));
    return a;
}

__device__ __forceinline__ void ldsm4(uint32_t* r, uint32_t addr) {
    asm volatile("ldmatrix.sync.aligned.m8n8.x4.shared.b16 {%0,%1,%2,%3}, [%4];"
        : "=r"(r[0]), "=r"(r[1]), "=r"(r[2]), "=r"(r[3]) : "r"(addr));
}

__device__ __forceinline__ void mma_bf16(float* c, const uint32_t* a,
                                         uint32_t b0, uint32_t b1) {
    asm volatile(
        "mma.sync.aligned.m16n8k16.row.col.f32.bf16.bf16.f32 "
        "{%0,%1,%2,%3}, {%4,%5,%6,%7}, {%8,%9}, {%0,%1,%2,%3};\n"
        : "+f"(c[0]), "+f"(c[1]), "+f"(c[2]), "+f"(c[3])
        : "r"(a[0]), "r"(a[1]), "r"(a[2]), "r"(a[3]), "r"(b0), "r"(b1));
}

// ---------------------------------------------------------------------------
// Kernel 1: token projection. Grid (4, 32), 512 threads. (unchanged)
// ---------------------------------------------------------------------------
__global__ void __launch_bounds__(512) token_proj(
    const float* __restrict__ token,
    const float* __restrict__ ln1_g,
    const float* __restrict__ ln1_b,
    const float* __restrict__ w_tok,
    const float* __restrict__ b_tok)
{
    __shared__ float st[768];
    __shared__ float sred[16];
    __shared__ float sredq[16];
    __shared__ float spart[16][33];

    const int b = blockIdx.y, nq = blockIdx.x;
    const int tid = threadIdx.x;
    const int wid = tid >> 5, lane = tid & 31;
    const float* trow = token + b * 768;

    float s = 0.f, sq = 0.f;
    for (int i = tid; i < 768; i += 512) {
        float v = trow[i];
        st[i] = v;
        s += v; sq += v * v;
    }
    #pragma unroll
    for (int o = 16; o; o >>= 1) {
        s  += __shfl_down_sync(FULL, s,  o);
        sq += __shfl_down_sync(FULL, sq, o);
    }
    if (lane == 0) { sred[wid] = s; sredq[wid] = sq; }
    __syncthreads();
    if (tid == 0) {
        float ts = 0.f, tq = 0.f;
        #pragma unroll
        for (int i = 0; i < 16; i++) { ts += sred[i]; tq += sredq[i]; }
        sred[0] = ts; sredq[0] = tq;
    }
    __syncthreads();
    const float mean = sred[0] * (1.0f / 768.0f);
    const float var  = sredq[0] * (1.0f / 768.0f) - mean * mean;
    const float rstd = rsqrtf(var + 1e-6f);
    for (int i = tid; i < 768; i += 512)
        st[i] = (st[i] - mean) * rstd * ln1_g[i] + ln1_b[i];
    __syncthreads();

    const int col = nq * 32 + lane;
    const int ks = wid;
    float acc = 0.f;
    const float* sp = st + ks * 48;
    const float* wp = w_tok + (size_t)(ks * 48) * 128 + col;
    #pragma unroll
    for (int kk = 0; kk < 48; kk++)
        acc += sp[kk] * wp[(size_t)kk * 128];
    spart[ks][lane] = acc;
    __syncthreads();

    if (tid < 32) {
        float z = b_tok[nq * 32 + tid];
        #pragma unroll
        for (int i = 0; i < 16; i++) z += spart[i][tid];
        g_y[b * 128 + nq * 32 + tid] = gelu_exact(z);
    }
}

// ---------------------------------------------------------------------------
// Kernel 2: persistent fused main. 512 thr = 2 independent 8-warp groups.
// ONE barrier per tile (R14 schedule). Phase1/3 use 8-lanes-per-row layout:
//   row = gw*4 + (lane>>3), sublane sl = lane&7, cols c = 2*sl + 16*j.
// Row reductions: 3 xor-shuffles. Phase3 scale per-lane via broadcast LDS.
// GEMM: warp tile 16x32 (rowg=gw&1, colg=gw>>1), bf16 hi/lo 3-term, ldmatrix.
//
// SMEM identical to R14.
// ---------------------------------------------------------------------------
#define A_STRIDE 400
#define A_PLANE  12800
#define A_BUFSZ  25600
#define A_GROUP  51200
#define OFF_B    102400
#define B_PLANE  51200
#define OFF_SH   204800
#define SH_SG2   0
#define SH_SB2   192
#define SH_SG3   384
#define SH_SB3   576
#define SH_INVNY 768
#define SH_WORDS 800
#define OFF_GF   (OFF_SH + SH_WORDS * 4)
#define GF_WORDS 704
#define GF_SMEAN 0       // [3][32]
#define GF_SVAR  96      // [3][32]
#define GF_SDOT  192     // [2][4][32]
#define GF_SSQ   448     // [2][4][32]
#define SMEM_BYTES (OFF_GF + 2 * GF_WORDS * 4)
#define NT32 4096

__global__ void __launch_bounds__(512, 1) main_kernel(
    const float* __restrict__ x,
    const float* __restrict__ p,
    const float* __restrict__ alpha,
    const float* __restrict__ ln2_g, const float* __restrict__ ln2_b,
    const float* __restrict__ w_x,  const float* __restrict__ b_x,
    const float* __restrict__ ln3_g, const float* __restrict__ ln3_b,
    float* __restrict__ out)
{
    extern __shared__ char smc[];
    const uint32_t sbase = smem_u32(smc);
    float* sh = (float*)(smc + OFF_SH);

    const int tid = threadIdx.x;
    const int wid = tid >> 5, lane = tid & 31;
    const int grp = wid >> 3, gw = wid & 7;
    const int g = lane >> 2, t4 = lane & 3;
    const int rowg = gw & 1, colg = gw >> 1;
    const int sl = lane & 7;              // sublane within row
    const int myrow = gw * 4 + (lane >> 3);   // phase1/3 row
    float* gf = (float*)(smc + OFF_GF + grp * GF_WORDS * 4);

    // ---- shared setup (full block) ----
    if (tid < 192) {
        sh[SH_SG2 + tid] = ln2_g[tid]; sh[SH_SB2 + tid] = ln2_b[tid];
        sh[SH_SG3 + tid] = ln3_g[tid]; sh[SH_SB3 + tid] = ln3_b[tid];
    }
    {   // B[n][k] = w_x[k][n], split bf16 hi/lo planes
        for (int i = tid; i < 192 * 128; i += 512) {
            const int k = i >> 7, n = i & 127;
            const float vv = w_x[i];
            __nv_bfloat16 h = __float2bfloat16(vv);
            __nv_bfloat16 l = __float2bfloat16(vv - __bfloat162float(h));
            *(__nv_bfloat16*)(smc + OFF_B + n * A_STRIDE + k * 2) = h;
            *(__nv_bfloat16*)(smc + OFF_B + B_PLANE + n * A_STRIDE + k * 2) = l;
        }
    }
    {   // 1/max(||y||,eps) per batch
        const int bb = wid * 2 + (lane >> 4);
        const int l16 = lane & 15;
        float q = 0.f;
        #pragma unroll
        for (int jj = 0; jj < 8; jj++) {
            const float v = g_y[bb * 128 + l16 + jj * 16];
            q += v * v;
        }
        #pragma unroll
        for (int o = 8; o; o >>= 1) q += __shfl_down_sync(FULL, q, o, 16);
        if (l16 == 0) sh[SH_INVNY + bb] = 1.0f / fmaxf(sqrtf(q), 1e-12f);
    }
    const float expAlpha = expf(alpha[0]);
    float2 bx[4];
    #pragma unroll
    for (int nt = 0; nt < 4; nt++)
        bx[nt] = *(const float2*)&b_x[colg * 32 + nt * 8 + t4 * 2];
    __syncthreads();   // last full-block barrier; groups now independent

    #define GBAR() asm volatile("bar.sync %0, 256;" :: "r"(grp + 1) : "memory")

    // ldmatrix per-thread offsets (buffer-invariant parts)
    const uint32_t aRowOff = (uint32_t)((rowg * 16 + (lane & 15)) * A_STRIDE
                                        + (lane >> 4) * 16);
    const uint32_t aGrpBase = sbase + grp * A_GROUP;
    const uint32_t bA0 = sbase + OFF_B
        + (uint32_t)((colg * 32 + (lane & 7) + ((lane >> 4) & 1) * 8) * A_STRIDE
                     + ((lane >> 3) & 1) * 16);
    const uint32_t bA1 = bA0 + 16 * A_STRIDE;

    const int step = gridDim.x * 2;
    const int t0 = blockIdx.x * 2 + grp;

    // phase1: LN2 + bf16 hi/lo planes. 8 lanes per row, cols c = 2*sl+16*j.
    auto do_phase1 = [&](float2 (&vv)[12], int abuf, int slot) {
        char* AhiP = smc + grp * A_GROUP + abuf * A_BUFSZ;
        char* AloP = AhiP + A_PLANE;
        float s = 0.f, sq = 0.f;
        #pragma unroll
        for (int j = 0; j < 12; j++) {
            s += vv[j].x + vv[j].y;
            sq += vv[j].x * vv[j].x + vv[j].y * vv[j].y;
        }
        #pragma unroll
        for (int o = 1; o < 8; o <<= 1) {
            s  += __shfl_xor_sync(FULL, s,  o);
            sq += __shfl_xor_sync(FULL, sq, o);
        }
        const float mean = s * (1.0f / 192.0f);
        const float var  = sq * (1.0f / 192.0f) - mean * mean;
        const float rstd = rsqrtf(var + 1e-6f);
        if (sl == 0) {
            gf[GF_SMEAN + slot * 32 + myrow] = mean;
            gf[GF_SVAR  + slot * 32 + myrow] = var;
        }
        #pragma unroll
        for (int j = 0; j < 12; j++) {
            const int c = 2 * sl + 16 * j;
            const float2 gg = *(const float2*)&sh[SH_SG2 + c];
            const float2 bb = *(const float2*)&sh[SH_SB2 + c];
            const float a0 = (vv[j].x - mean) * rstd * gg.x + bb.x;
            const float a1 = (vv[j].y - mean) * rstd * gg.y + bb.y;
            __nv_bfloat162 h2 = __floats2bfloat162_rn(a0, a1);
            __nv_bfloat162 l2 = __floats2bfloat162_rn(a0 - __low2float(h2),
                                                      a1 - __high2float(h2));
            const int off = myrow * A_STRIDE + 4 * sl + 32 * j;
            *(uint32_t*)(AhiP + off) = *(uint32_t*)&h2;
            *(uint32_t*)(AloP + off) = *(uint32_t*)&l2;
        }
    };

    // ---- prologue: prefetch + phase1 of first tile ----
    float2 v[12], vn[12];
    {
        const int tpf = (t0 < NT32) ? t0 : 0;
        const float2* xr = (const float2*)(x + ((size_t)tpf * 32 + myrow) * 192);
        #pragma unroll
        for (int j = 0; j < 12; j++) v[j] = xr[sl + 8 * j];
    }
    if (t0 < NT32) do_phase1(v, 0, 0);
    GBAR();

    int it = 0, s_cur = 0;
    for (int cur = t0; cur < NT32; cur += step, it++) {
        const int ab = it & 1;
        const int s_nxt = (s_cur == 2) ? 0 : s_cur + 1;
        const int b = cur >> 7;
        const size_t base = (size_t)cur * 32 * 192;
        const int nxt = cur + step;

        // per-tile scalar prefetch (consumed after GEMM)
        float2 stn[4];
        #pragma unroll
        for (int nt = 0; nt < 4; nt++)
            stn[nt] = *(const float2*)&g_y[b * 128 + colg * 32 + nt * 8 + t4 * 2];
        const float pb = p[b];
        const float invny = sh[SH_INVNY + b];

        // prefetch next tile's x (covered by GEMM)
        {
            const int tpf = (nxt < NT32) ? nxt : cur;
            const float2* xr = (const float2*)(x + ((size_t)tpf * 32 + myrow) * 192);
            #pragma unroll
            for (int j = 0; j < 12; j++) vn[j] = xr[sl + 8 * j];
        }

        // ---- GEMM(cur): warp tile 16x32, 12 k16-steps, 3 terms ----
        const uint32_t aHiA = aGrpBase + ab * A_BUFSZ + aRowOff;
        const uint32_t aLoA = aHiA + A_PLANE;
        float acc[4][4];
        #pragma unroll
        for (int nt = 0; nt < 4; nt++)
            #pragma unroll
            for (int i = 0; i < 4; i++) acc[nt][i] = 0.f;

        #pragma unroll
        for (int ks = 0; ks < 12; ks++) {
            const uint32_t kb = ks * 32;
            uint32_t aH[4], aL[4], bH0[4], bH1[4], bL0[4], bL1[4];
            ldsm4(aH,  aHiA + kb);
            ldsm4(bH0, bA0 + kb);
            ldsm4(bH1, bA1 + kb);
            ldsm4(aL,  aLoA + kb);
            ldsm4(bL0, bA0 + B_PLANE + kb);
            ldsm4(bL1, bA1 + B_PLANE + kb);
            mma_bf16(acc[0], aH, bH0[0], bH0[1]);
            mma_bf16(acc[1], aH, bH0[2], bH0[3]);
            mma_bf16(acc[2], aH, bH1[0], bH1[1]);
            mma_bf16(acc[3], aH, bH1[2], bH1[3]);
            mma_bf16(acc[0], aH, bL0[0], bL0[1]);
            mma_bf16(acc[1], aH, bL0[2], bL0[3]);
            mma_bf16(acc[2], aH, bL1[0], bL1[1]);
            mma_bf16(acc[3], aH, bL1[2], bL1[3]);
            mma_bf16(acc[0], aL, bH0[0], bH0[1]);
            mma_bf16(acc[1], aL, bH0[2], bH0[3]);
            mma_bf16(acc[2], aL, bH1[0], bH1[1]);
            mma_bf16(acc[3], aL, bH1[2], bH1[3]);
        }

        // ---- Epilogue(cur): gelu, dot/ssq partials -> pbuf ab ----
        #pragma unroll
        for (int h = 0; h < 2; h++) {
            float dot = 0.f, ssq = 0.f;
            #pragma unroll
            for (int nt = 0; nt < 4; nt++) {
                #pragma unroll
                for (int c2 = 0; c2 < 2; c2++) {
                    const float z = acc[nt][h * 2 + c2]
                                  + (c2 ? bx[nt].y : bx[nt].x);
                    const float e = gelu_fast(z);
                    dot += e * (c2 ? stn[nt].y : stn[nt].x);
                    ssq += e * e;
                }
            }
            dot += __shfl_xor_sync(FULL, dot, 1);
            dot += __shfl_xor_sync(FULL, dot, 2);
            ssq += __shfl_xor_sync(FULL, ssq, 1);
            ssq += __shfl_xor_sync(FULL, ssq, 2);
            if (t4 == 0) {
                const int row = rowg * 16 + h * 8 + g;
                gf[GF_SDOT + ab * 128 + colg * 32 + row] = dot;
                gf[GF_SSQ  + ab * 128 + colg * 32 + row] = ssq;
            }
        }

        // ---- phase1(nxt) into the other A buffer / next stat slot ----
        if (nxt < NT32) do_phase1(vn, ab ^ 1, s_nxt);

        GBAR();   // publishes: partials(cur), A(nxt), stats(nxt)

        // ---- scale(cur): per-lane from broadcast LDS, then phase3(cur) ----
        {
            float dot = 0.f, ssq = 0.f;
            #pragma unroll
            for (int c = 0; c < 4; c++) {
                dot += gf[GF_SDOT + ab * 128 + c * 32 + myrow];
                ssq += gf[GF_SSQ  + ab * 128 + c * 32 + myrow];
            }
            const float ps = pb * expAlpha * invny;
            const float a  = ps * dot / fmaxf(sqrtf(ssq), 1e-12f);
            // LN3(a*x) = (x - m) * a * rsqrt(a^2 v + eps) * g3 + b3
            const float scv = a * rsqrtf(a * a * gf[GF_SVAR + s_cur * 32 + myrow] + 1e-6f);
            const float m   = gf[GF_SMEAN + s_cur * 32 + myrow];

            float* ob = out + base + (size_t)myrow * 192;
            #pragma unroll
            for (int j = 0; j < 12; j++) {
                const int c = 2 * sl + 16 * j;
                const float2 g3 = *(const float2*)&sh[SH_SG3 + c];
                const float2 b3 = *(const float2*)&sh[SH_SB3 + c];
                const float2 xv = v[j];
                float2 o;
                o.x = 0.5f * xv.x + (xv.x - m) * scv * g3.x + b3.x;
                o.y = 0.5f * xv.y + (xv.y - m) * scv * g3.y + b3.y;
                *(float2*)&ob[c] = o;
            }
        }
        // rotate prefetched tile into current
        #pragma unroll
        for (int j = 0; j < 12; j++) v[j] = vn[j];
        s_cur = s_nxt;
        // Hazards identical to R14 (A double-buffer, partials double-buffer,
        // stats triple-buffer; one barrier separates every producer/consumer).
    }
    #undef GBAR
}

// ---------------------------------------------------------------------------
extern "C" void kernel_launch(void* const* d_in, const int* in_sizes, int n_in,
                              void* d_out, int out_size)
{
    (void)in_sizes; (void)n_in; (void)out_size;
    const float* x     = (const float*)d_in[0];
    const float* token = (const float*)d_in[1];
    const float* p     = (const float*)d_in[2];
    const float* alpha = (const float*)d_in[3];
    const float* ln1_g = (const float*)d_in[4];
    const float* ln1_b = (const float*)d_in[5];
    const float* w_tok = (const float*)d_in[6];
    const float* b_tok = (const float*)d_in[7];
    const float* ln2_g = (const float*)d_in[8];
    const float* ln2_b = (const float*)d_in[9];
    const float* w_x   = (const float*)d_in[10];
    const float* b_x   = (const float*)d_in[11];
    const float* ln3_g = (const float*)d_in[12];
    const float* ln3_b = (const float*)d_in[13];
    float* out = (float*)d_out;

    token_proj<<<dim3(4, 32), 512>>>(token, ln1_g, ln1_b, w_tok, b_tok);

    static int nsm = 0;
    if (nsm == 0) {
        cudaDeviceGetAttribute(&nsm, cudaDevAttrMultiProcessorCount, 0);
        if (nsm <= 0) nsm = 148;
        cudaFuncSetAttribute(main_kernel,
                             cudaFuncAttributeMaxDynamicSharedMemorySize,
                             SMEM_BYTES);
    }
    main_kernel<<<nsm, 512, SMEM_BYTES>>>(x, p, alpha, ln2_g, ln2_b, w_x, b_x,
                                          ln3_g, ln3_b, out);
}

// round 16
// speedup vs baseline: 1.0451x; 1.0451x over previous
#include <cuda_runtime.h>
#include <cuda_bf16.h>
#include <math.h>
#include <stdint.h>

#define FULL 0xffffffffu

__device__ float g_y[32 * 128];   // gelu(LN1(token) @ w_tok + b_tok), unnormalized

__device__ __forceinline__ float gelu_exact(float z) {
    return 0.5f * z * (1.0f + erff(z * 0.70710678118654752f));
}

// Branch-free gelu via Abramowitz-Stegun 7.1.26 erf (|eps| < 1.5e-7 abs).
__device__ __forceinline__ float gelu_fast(float z) {
    const float xs = fabsf(z) * 0.70710678118654752f;
    const float t = __fdividef(1.0f, fmaf(0.3275911f, xs, 1.0f));
    float poly = fmaf(1.061405429f, t, -1.453152027f);
    poly = fmaf(poly, t, 1.421413741f);
    poly = fmaf(poly, t, -0.284496736f);
    poly = fmaf(poly, t, 0.254829592f);
    poly *= t;
    const float erfc_v = poly * __expf(-xs * xs);   // 1 - erf(xs), xs >= 0
    const float hz = 0.5f * z;
    return (z >= 0.f) ? hz * (2.0f - erfc_v) : hz * erfc_v;
}

__device__ __forceinline__ uint32_t smem_u32(const void* p) {
    uint32_t a;
    asm("{ .reg .u64 t; cvta.to.shared.u64 t, %1; cvt.u32.u64 %0, t; }"
        : "=r"(a) : "l"(p));
    return a;
}

__device__ __forceinline__ void ldsm4(uint32_t* r, uint32_t addr) {
    asm volatile("ldmatrix.sync.aligned.m8n8.x4.shared.b16 {%0,%1,%2,%3}, [%4];"
        : "=r"(r[0]), "=r"(r[1]), "=r"(r[2]), "=r"(r[3]) : "r"(addr));
}

__device__ __forceinline__ void mma_bf16(float* c, const uint32_t* a,
                                         uint32_t b0, uint32_t b1) {
    asm volatile(
        "mma.sync.aligned.m16n8k16.row.col.f32.bf16.bf16.f32 "
        "{%0,%1,%2,%3}, {%4,%5,%6,%7}, {%8,%9}, {%0,%1,%2,%3};\n"
        : "+f"(c[0]), "+f"(c[1]), "+f"(c[2]), "+f"(c[3])
        : "r"(a[0]), "r"(a[1]), "r"(a[2]), "r"(a[3]), "r"(b0), "r"(b1));
}

// ---------------------------------------------------------------------------
// Kernel 1: token projection. Grid (4, 32), 512 threads.
// ---------------------------------------------------------------------------
__global__ void __launch_bounds__(512) token_proj(
    const float* __restrict__ token,
    const float* __restrict__ ln1_g,
    const float* __restrict__ ln1_b,
    const float* __restrict__ w_tok,
    const float* __restrict__ b_tok)
{
    __shared__ float st[768];
    __shared__ float sred[16];
    __shared__ float sredq[16];
    __shared__ float spart[16][33];

    const int b = blockIdx.y, nq = blockIdx.x;
    const int tid = threadIdx.x;
    const int wid = tid >> 5, lane = tid & 31;
    const float* trow = token + b * 768;

    float s = 0.f, sq = 0.f;
    for (int i = tid; i < 768; i += 512) {
        float v = trow[i];
        st[i] = v;
        s += v; sq += v * v;
    }
    #pragma unroll
    for (int o = 16; o; o >>= 1) {
        s  += __shfl_down_sync(FULL, s,  o);
        sq += __shfl_down_sync(FULL, sq, o);
    }
    if (lane == 0) { sred[wid] = s; sredq[wid] = sq; }
    __syncthreads();
    if (tid == 0) {
        float ts = 0.f, tq = 0.f;
        #pragma unroll
        for (int i = 0; i < 16; i++) { ts += sred[i]; tq += sredq[i]; }
        sred[0] = ts; sredq[0] = tq;
    }
    __syncthreads();
    const float mean = sred[0] * (1.0f / 768.0f);
    const float var  = sredq[0] * (1.0f / 768.0f) - mean * mean;
    const float rstd = rsqrtf(var + 1e-6f);
    for (int i = tid; i < 768; i += 512)
        st[i] = (st[i] - mean) * rstd * ln1_g[i] + ln1_b[i];
    __syncthreads();

    const int col = nq * 32 + lane;
    const int ks = wid;
    float acc = 0.f;
    const float* sp = st + ks * 48;
    const float* wp = w_tok + (size_t)(ks * 48) * 128 + col;
    #pragma unroll
    for (int kk = 0; kk < 48; kk++)
        acc += sp[kk] * wp[(size_t)kk * 128];
    spart[ks][lane] = acc;
    __syncthreads();

    if (tid < 32) {
        float z = b_tok[nq * 32 + tid];
        #pragma unroll
        for (int i = 0; i < 16; i++) z += spart[i][tid];
        g_y[b * 128 + nq * 32 + tid] = gelu_exact(z);
    }
}

// ---------------------------------------------------------------------------
// Kernel 2: persistent fused main. 512 thr = 2 independent 8-warp groups.
// ONE barrier per tile (R14 schedule, R14 memory layout):
//   GEMM(i)[Abuf i%2] -> epilogue(i) partials STS -> phase1(i+1)[Abuf (i+1)%2]
//   -> GBAR -> scale(i)+phase3(i) -> rotate
// gelu_fast in the epilogue (only change vs R14).
// ---------------------------------------------------------------------------
#define A_STRIDE 400
#define A_PLANE  12800
#define A_BUFSZ  25600
#define A_GROUP  51200
#define OFF_B    102400
#define B_PLANE  51200
#define OFF_SH   204800
#define SH_SG2   0
#define SH_SB2   192
#define SH_SG3   384
#define SH_SB3   576
#define SH_INVNY 768
#define SH_WORDS 800
#define OFF_GF   (OFF_SH + SH_WORDS * 4)
#define GF_WORDS 704
#define GF_SMEAN 0       // [3][32]
#define GF_SVAR  96      // [3][32]
#define GF_SDOT  192     // [2][4][32]
#define GF_SSQ   448     // [2][4][32]
#define SMEM_BYTES (OFF_GF + 2 * GF_WORDS * 4)
#define NT32 4096

__global__ void __launch_bounds__(512, 1) main_kernel(
    const float* __restrict__ x,
    const float* __restrict__ p,
    const float* __restrict__ alpha,
    const float* __restrict__ ln2_g, const float* __restrict__ ln2_b,
    const float* __restrict__ w_x,  const float* __restrict__ b_x,
    const float* __restrict__ ln3_g, const float* __restrict__ ln3_b,
    float* __restrict__ out)
{
    extern __shared__ char smc[];
    const uint32_t sbase = smem_u32(smc);
    float* sh = (float*)(smc + OFF_SH);

    const int tid = threadIdx.x;
    const int wid = tid >> 5, lane = tid & 31;
    const int grp = wid >> 3, gw = wid & 7;
    const int g = lane >> 2, t4 = lane & 3;
    const int rowg = gw & 1, colg = gw >> 1;
    float* gf = (float*)(smc + OFF_GF + grp * GF_WORDS * 4);

    // ---- shared setup (full block) ----
    if (tid < 192) {
        sh[SH_SG2 + tid] = ln2_g[tid]; sh[SH_SB2 + tid] = ln2_b[tid];
        sh[SH_SG3 + tid] = ln3_g[tid]; sh[SH_SB3 + tid] = ln3_b[tid];
    }
    {   // B[n][k] = w_x[k][n], split bf16 hi/lo planes
        for (int i = tid; i < 192 * 128; i += 512) {
            const int k = i >> 7, n = i & 127;
            const float vv = w_x[i];
            __nv_bfloat16 h = __float2bfloat16(vv);
            __nv_bfloat16 l = __float2bfloat16(vv - __bfloat162float(h));
            *(__nv_bfloat16*)(smc + OFF_B + n * A_STRIDE + k * 2) = h;
            *(__nv_bfloat16*)(smc + OFF_B + B_PLANE + n * A_STRIDE + k * 2) = l;
        }
    }
    {   // 1/max(||y||,eps) per batch
        const int bb = wid * 2 + (lane >> 4);
        const int l16 = lane & 15;
        float q = 0.f;
        #pragma unroll
        for (int jj = 0; jj < 8; jj++) {
            const float v = g_y[bb * 128 + l16 + jj * 16];
            q += v * v;
        }
        #pragma unroll
        for (int o = 8; o; o >>= 1) q += __shfl_down_sync(FULL, q, o, 16);
        if (l16 == 0) sh[SH_INVNY + bb] = 1.0f / fmaxf(sqrtf(q), 1e-12f);
    }
    const float expAlpha = expf(alpha[0]);
    float2 bx[4];
    #pragma unroll
    for (int nt = 0; nt < 4; nt++)
        bx[nt] = *(const float2*)&b_x[colg * 32 + nt * 8 + t4 * 2];
    __syncthreads();   // last full-block barrier; groups now independent

    #define GBAR() asm volatile("bar.sync %0, 256;" :: "r"(grp + 1) : "memory")

    // ldmatrix per-thread offsets (buffer-invariant parts)
    const uint32_t aRowOff = (uint32_t)((rowg * 16 + (lane & 15)) * A_STRIDE
                                        + (lane >> 4) * 16);
    const uint32_t aGrpBase = sbase + grp * A_GROUP;
    const uint32_t bA0 = sbase + OFF_B
        + (uint32_t)((colg * 32 + (lane & 7) + ((lane >> 4) & 1) * 8) * A_STRIDE
                     + ((lane >> 3) & 1) * 16);
    const uint32_t bA1 = bA0 + 16 * A_STRIDE;

    const int step = gridDim.x * 2;
    const int t0 = blockIdx.x * 2 + grp;

    // phase1: LN2 + bf16 hi/lo planes from registers into A buffer/stat slot
    auto do_phase1 = [&](float2 (&vv)[4][3], int abuf, int slot) {
        char* AhiP = smc + grp * A_GROUP + abuf * A_BUFSZ;
        char* AloP = AhiP + A_PLANE;
        #pragma unroll
        for (int rr = 0; rr < 4; rr++) {
            const int r = gw * 4 + rr;
            float s = 0.f, sq = 0.f;
            #pragma unroll
            for (int j = 0; j < 3; j++) {
                s += vv[rr][j].x + vv[rr][j].y;
                sq += vv[rr][j].x * vv[rr][j].x + vv[rr][j].y * vv[rr][j].y;
            }
            #pragma unroll
            for (int o = 16; o; o >>= 1) {
                s  += __shfl_xor_sync(FULL, s,  o);
                sq += __shfl_xor_sync(FULL, sq, o);
            }
            const float mean = s * (1.0f / 192.0f);
            const float var  = sq * (1.0f / 192.0f) - mean * mean;
            const float rstd = rsqrtf(var + 1e-6f);
            if (lane == 0) {
                gf[GF_SMEAN + slot * 32 + r] = mean;
                gf[GF_SVAR  + slot * 32 + r] = var;
            }
            #pragma unroll
            for (int j = 0; j < 3; j++) {
                const int c = 2 * lane + 64 * j;
                const float a0 = (vv[rr][j].x - mean) * rstd * sh[SH_SG2 + c]     + sh[SH_SB2 + c];
                const float a1 = (vv[rr][j].y - mean) * rstd * sh[SH_SG2 + c + 1] + sh[SH_SB2 + c + 1];
                __nv_bfloat162 h2 = __floats2bfloat162_rn(a0, a1);
                __nv_bfloat162 l2 = __floats2bfloat162_rn(a0 - __low2float(h2),
                                                          a1 - __high2float(h2));
                const int off = r * A_STRIDE + 4 * lane + 128 * j;
                *(uint32_t*)(AhiP + off) = *(uint32_t*)&h2;
                *(uint32_t*)(AloP + off) = *(uint32_t*)&l2;
            }
        }
    };

    // ---- prologue: prefetch + phase1 of first tile ----
    float2 v[4][3], vn[4][3];
    {
        const int tpf = (t0 < NT32) ? t0 : 0;
        const float2* xr = (const float2*)(x + ((size_t)tpf * 32 + gw * 4) * 192);
        #pragma unroll
        for (int rr = 0; rr < 4; rr++)
            #pragma unroll
            for (int j = 0; j < 3; j++)
                v[rr][j] = xr[rr * 96 + lane + 32 * j];
    }
    if (t0 < NT32) do_phase1(v, 0, 0);
    GBAR();

    int it = 0, s_cur = 0;
    for (int cur = t0; cur < NT32; cur += step, it++) {
        const int ab = it & 1;
        const int s_nxt = (s_cur == 2) ? 0 : s_cur + 1;
        const int b = cur >> 7;
        const size_t base = (size_t)cur * 32 * 192;
        const int nxt = cur + step;

        // per-tile scalar prefetch (consumed after GEMM)
        float2 stn[4];
        #pragma unroll
        for (int nt = 0; nt < 4; nt++)
            stn[nt] = *(const float2*)&g_y[b * 128 + colg * 32 + nt * 8 + t4 * 2];
        const float pb = p[b];
        const float invny = sh[SH_INVNY + b];

        // prefetch next tile's x (covered by GEMM)
        {
            const int tpf = (nxt < NT32) ? nxt : cur;
            const float2* xr = (const float2*)(x + ((size_t)tpf * 32 + gw * 4) * 192);
            #pragma unroll
            for (int rr = 0; rr < 4; rr++)
                #pragma unroll
                for (int j = 0; j < 3; j++)
                    vn[rr][j] = xr[rr * 96 + lane + 32 * j];
        }

        // ---- GEMM(cur): warp tile 16x32, 12 k16-steps, 3 terms ----
        const uint32_t aHiA = aGrpBase + ab * A_BUFSZ + aRowOff;
        const uint32_t aLoA = aHiA + A_PLANE;
        float acc[4][4];
        #pragma unroll
        for (int nt = 0; nt < 4; nt++)
            #pragma unroll
            for (int i = 0; i < 4; i++) acc[nt][i] = 0.f;

        #pragma unroll
        for (int ks = 0; ks < 12; ks++) {
            const uint32_t kb = ks * 32;
            uint32_t aH[4], aL[4], bH0[4], bH1[4], bL0[4], bL1[4];
            ldsm4(aH,  aHiA + kb);
            ldsm4(bH0, bA0 + kb);
            ldsm4(bH1, bA1 + kb);
            ldsm4(aL,  aLoA + kb);
            ldsm4(bL0, bA0 + B_PLANE + kb);
            ldsm4(bL1, bA1 + B_PLANE + kb);
            mma_bf16(acc[0], aH, bH0[0], bH0[1]);
            mma_bf16(acc[1], aH, bH0[2], bH0[3]);
            mma_bf16(acc[2], aH, bH1[0], bH1[1]);
            mma_bf16(acc[3], aH, bH1[2], bH1[3]);
            mma_bf16(acc[0], aH, bL0[0], bL0[1]);
            mma_bf16(acc[1], aH, bL0[2], bL0[3]);
            mma_bf16(acc[2], aH, bL1[0], bL1[1]);
            mma_bf16(acc[3], aH, bL1[2], bL1[3]);
            mma_bf16(acc[0], aL, bH0[0], bH0[1]);
            mma_bf16(acc[1], aL, bH0[2], bH0[3]);
            mma_bf16(acc[2], aL, bH1[0], bH1[1]);
            mma_bf16(acc[3], aL, bH1[2], bH1[3]);
        }

        // ---- Epilogue(cur): gelu_fast, dot/ssq partials -> pbuf ab ----
        #pragma unroll
        for (int h = 0; h < 2; h++) {
            float dot = 0.f, ssq = 0.f;
            #pragma unroll
            for (int nt = 0; nt < 4; nt++) {
                #pragma unroll
                for (int c2 = 0; c2 < 2; c2++) {
                    const float z = acc[nt][h * 2 + c2]
                                  + (c2 ? bx[nt].y : bx[nt].x);
                    const float e = gelu_fast(z);
                    dot += e * (c2 ? stn[nt].y : stn[nt].x);
                    ssq += e * e;
                }
            }
            dot += __shfl_xor_sync(FULL, dot, 1);
            dot += __shfl_xor_sync(FULL, dot, 2);
            ssq += __shfl_xor_sync(FULL, ssq, 1);
            ssq += __shfl_xor_sync(FULL, ssq, 2);
            if (t4 == 0) {
                const int row = rowg * 16 + h * 8 + g;
                gf[GF_SDOT + ab * 128 + colg * 32 + row] = dot;
                gf[GF_SSQ  + ab * 128 + colg * 32 + row] = ssq;
            }
        }

        // ---- phase1(nxt) into the other A buffer / next stat slot ----
        if (nxt < NT32) do_phase1(vn, ab ^ 1, s_nxt);

        GBAR();   // publishes: partials(cur), A(nxt), stats(nxt)

        // ---- scale(cur) per warp, then phase3(cur) from registers ----
        float myMean, mySc;
        {
            const int row = gw * 4 + (lane & 3);
            float dot = 0.f, ssq = 0.f;
            #pragma unroll
            for (int c = 0; c < 4; c++) {
                dot += gf[GF_SDOT + ab * 128 + c * 32 + row];
                ssq += gf[GF_SSQ  + ab * 128 + c * 32 + row];
            }
            const float ps = pb * expAlpha * invny;
            const float a  = ps * dot / fmaxf(sqrtf(ssq), 1e-12f);
            // LN3(a*x) = (x - m) * a * rsqrt(a^2 v + eps) * g3 + b3
            mySc = a * rsqrtf(a * a * gf[GF_SVAR + s_cur * 32 + row] + 1e-6f);
            myMean = gf[GF_SMEAN + s_cur * 32 + row];
        }
        {
            float* ob = out + base;
            #pragma unroll
            for (int rr = 0; rr < 4; rr++) {
                const int r = gw * 4 + rr;
                const float m   = __shfl_sync(FULL, myMean, rr);
                const float scv = __shfl_sync(FULL, mySc, rr);
                #pragma unroll
                for (int j = 0; j < 3; j++) {
                    const int c = 2 * lane + 64 * j;
                    const float2 xv = v[rr][j];
                    float2 o;
                    o.x = 0.5f * xv.x + (xv.x - m) * scv * sh[SH_SG3 + c]     + sh[SH_SB3 + c];
                    o.y = 0.5f * xv.y + (xv.y - m) * scv * sh[SH_SG3 + c + 1] + sh[SH_SB3 + c + 1];
                    *(float2*)&ob[r * 192 + c] = o;
                }
            }
        }
        // rotate prefetched tile into current
        #pragma unroll
        for (int rr = 0; rr < 4; rr++)
            #pragma unroll
            for (int j = 0; j < 3; j++)
                v[rr][j] = vn[rr][j];
        s_cur = s_nxt;
        // Hazards identical to R14 (A double-buffer, partials double-buffer,
        // stats triple-buffer; one barrier separates every producer/consumer).
    }
    #undef GBAR
}

// ---------------------------------------------------------------------------
extern "C" void kernel_launch(void* const* d_in, const int* in_sizes, int n_in,
                              void* d_out, int out_size)
{
    (void)in_sizes; (void)n_in; (void)out_size;
    const float* x     = (const float*)d_in[0];
    const float* token = (const float*)d_in[1];
    const float* p     = (const float*)d_in[2];
    const float* alpha = (const float*)d_in[3];
    const float* ln1_g = (const float*)d_in[4];
    const float* ln1_b = (const float*)d_in[5];
    const float* w_tok = (const float*)d_in[6];
    const float* b_tok = (const float*)d_in[7];
    const float* ln2_g = (const float*)d_in[8];
    const float* ln2_b = (const float*)d_in[9];
    const float* w_x   = (const float*)d_in[10];
    const float* b_x   = (const float*)d_in[11];
    const float* ln3_g = (const float*)d_in[12];
    const float* ln3_b = (const float*)d_in[13];
    float* out = (float*)d_out;

    token_proj<<<dim3(4, 32), 512>>>(token, ln1_g, ln1_b, w_tok, b_tok);

    static int nsm = 0;
    if (nsm == 0) {
        cudaDeviceGetAttribute(&nsm, cudaDevAttrMultiProcessorCount, 0);
        if (nsm <= 0) nsm = 148;
        cudaFuncSetAttribute(main_kernel,
                             cudaFuncAttributeMaxDynamicSharedMemorySize,
                             SMEM_BYTES);
    }
    main_kernel<<<nsm, 512, SMEM_BYTES>>>(x, p, alpha, ln2_g, ln2_b, w_x, b_x,
                                          ln3_g, ln3_b, out);
}